// round 11
// baseline (speedup 1.0000x reference)
#include <cuda_runtime.h>
#include <cstdint>

// ---------------------------------------------------------------------------
// FrameConsistencyLoss, single persistent kernel.
//
// Prologue (per CTA, redundant): stage W/bias in smem, compute 16 pair Gram
// matrices, per-warp Cholesky + solve + pack table into smem.
// Main loop: 1024-row tiles; histogram+counting-sort by (ea,eb) pair; warps
// grab pair-uniform 64-row fused items (one broadcast table stream feeds two
// row sets); rows read directly from global (L2-prefetched one tile ahead).
// ---------------------------------------------------------------------------

#define TILE   1024
#define NTHR   512
#define NWARP  16
#define MAXW   34

// table layout in ULLs
#define OFF_ULL   224
#define DIAG_BASE 2688
#define DIAG_ULL  56
#define SPRIME_U  2912
#define TAB_U     2920

typedef unsigned long long ull;

__device__ double g_sum;     // reset by last CTA each run
__device__ int    g_done;

__device__ __forceinline__ ull pk2(float lo, float hi) {
    ull r; asm("mov.b64 %0, {%1,%2};" : "=l"(r) : "f"(lo), "f"(hi)); return r;
}
__device__ __forceinline__ void upk2(ull v, float& lo, float& hi) {
    asm("mov.b64 {%0,%1}, %2;" : "=f"(lo), "=f"(hi) : "l"(v));
}
__device__ __forceinline__ ull ffma2(ull a, ull b, ull c) {
    ull d; asm("fma.rn.f32x2 %0, %1, %2, %3;" : "=l"(d) : "l"(a), "l"(b), "l"(c)); return d;
}

// f(j) = # table ulls in C-rows 0..j-1 (row m holds floor(m/2)+1 ulls)
__device__ __forceinline__ int frow(int j) {
    int q = j >> 1, r = j & 1;
    return j + q * (q - 1) + r * q;
}

struct Smem {
    ull   tab[TAB_U];            // packed eval tables (+ s' floats at SPRIME_U)
    float C[16][28][29];         // Gram -> Cholesky scratch
    float Mc[16][28];
    float cc[16];
    float Wst[4 * 14 * 64];      // staged W
    float Bst[4 * 64];           // staged bias
    int   order[TILE];
    int   pairv[TILE];
    int   count[16];
    int   ofs[16];
    int   wP[MAXW], wO[MAXW], wN[MAXW];
    int   num, item;
    float red[NWARP];
};

// ---------------------------------------------------------------------------
// evaluation (pack-over-k; fused variant shares table LDS across 2 row sets)
// ---------------------------------------------------------------------------
template<bool FUSED>
__device__ __forceinline__ float eval_off(const ull* __restrict__ T, float sp,
    const ull* __restrict__ A1, const ull* __restrict__ B1,
    const ull* __restrict__ A2, const ull* __restrict__ B2,
    bool v1, bool v2)
{
    ull S1[14], S2[14];
#pragma unroll
    for (int k = 0; k < 14; k++) { S1[k] = T[k]; if (FUSED) S2[k] = T[k]; }
    int idx = 14;
#pragma unroll
    for (int jj = 0; jj < 14; jj++) {
        ull w1 = (jj < 7) ? A1[jj] : B1[jj - 7];
        float lo1, hi1; upk2(w1, lo1, hi1);
        ull bl1 = pk2(lo1, lo1), bh1 = pk2(hi1, hi1);
        ull bl2 = 0, bh2 = 0;
        if (FUSED) {
            ull w2 = (jj < 7) ? A2[jj] : B2[jj - 7];
            float lo2, hi2; upk2(w2, lo2, hi2);
            bl2 = pk2(lo2, lo2); bh2 = pk2(hi2, hi2);
        }
#pragma unroll
        for (int kk = 0; kk <= jj; kk++) {
            ull t = T[idx + kk];
            S1[kk] = ffma2(t, bl1, S1[kk]);
            if (FUSED) S2[kk] = ffma2(t, bl2, S2[kk]);
        }
#pragma unroll
        for (int kk = 0; kk <= jj; kk++) {
            ull t = T[idx + jj + 1 + kk];
            S1[kk] = ffma2(t, bh1, S1[kk]);
            if (FUSED) S2[kk] = ffma2(t, bh2, S2[kk]);
        }
        idx += 2 * (jj + 1);
    }
    float L1 = sp, L2 = sp;
#pragma unroll
    for (int k = 0; k < 14; k++) {
        float lo, hi;
        upk2(S1[k], lo, hi); L1 = fmaf(lo, lo, L1); L1 = fmaf(hi, hi, L1);
        if (FUSED) { upk2(S2[k], lo, hi); L2 = fmaf(lo, lo, L2); L2 = fmaf(hi, hi, L2); }
    }
    float r = v1 ? L1 : 0.f;
    if (FUSED) r += v2 ? L2 : 0.f;
    return r;
}

template<bool FUSED>
__device__ __forceinline__ float eval_diag(const ull* __restrict__ T,
    const ull* __restrict__ A1, const ull* __restrict__ B1,
    const ull* __restrict__ A2, const ull* __restrict__ B2,
    bool v1, bool v2, ull neg1)
{
    ull u1[7], u2[7];
#pragma unroll
    for (int j = 0; j < 7; j++) {
        u1[j] = ffma2(B1[j], neg1, A1[j]);
        if (FUSED) u2[j] = ffma2(B2[j], neg1, A2[j]);
    }
    ull S1[7], S2[7];
    const ull z = pk2(0.f, 0.f);
#pragma unroll
    for (int k = 0; k < 7; k++) { S1[k] = z; if (FUSED) S2[k] = z; }
    int idx = 0;
#pragma unroll
    for (int jj = 0; jj < 7; jj++) {
        float lo1, hi1; upk2(u1[jj], lo1, hi1);
        ull bl1 = pk2(lo1, lo1), bh1 = pk2(hi1, hi1);
        ull bl2 = 0, bh2 = 0;
        if (FUSED) {
            float lo2, hi2; upk2(u2[jj], lo2, hi2);
            bl2 = pk2(lo2, lo2); bh2 = pk2(hi2, hi2);
        }
#pragma unroll
        for (int kk = 0; kk <= jj; kk++) {
            ull t = T[idx + kk];
            S1[kk] = ffma2(t, bl1, S1[kk]);
            if (FUSED) S2[kk] = ffma2(t, bl2, S2[kk]);
        }
#pragma unroll
        for (int kk = 0; kk <= jj; kk++) {
            ull t = T[idx + jj + 1 + kk];
            S1[kk] = ffma2(t, bh1, S1[kk]);
            if (FUSED) S2[kk] = ffma2(t, bh2, S2[kk]);
        }
        idx += 2 * (jj + 1);
    }
    float L1 = 0.f, L2 = 0.f;
#pragma unroll
    for (int k = 0; k < 7; k++) {
        float lo, hi;
        upk2(S1[k], lo, hi); L1 = fmaf(lo, lo, L1); L1 = fmaf(hi, hi, L1);
        if (FUSED) { upk2(S2[k], lo, hi); L2 = fmaf(lo, lo, L2); L2 = fmaf(hi, hi, L2); }
    }
    float r = v1 ? L1 : 0.f;
    if (FUSED) r += v2 ? L2 : 0.f;
    return r;
}

// ---------------------------------------------------------------------------

__global__ __launch_bounds__(NTHR, 1)
void main_kernel(const float* __restrict__ A, const float* __restrict__ Bv,
                 const int* __restrict__ ida, const int* __restrict__ idb,
                 int N, float* __restrict__ out)
{
    extern __shared__ char smemraw[];
    Smem* S = (Smem*)smemraw;
    const int tid = threadIdx.x, lane = tid & 31, wid = tid >> 5;

    // ================= prologue: build tables in smem =================
    for (int i = tid; i < 4 * 14 * 64; i += NTHR) S->Wst[i] = A == nullptr ? 0.f : 0.f; // placeholder overwritten below
    // stage W / bias (W passed via separate pointers below)
    // (Wst/Bst filled in kernel args version — see launch: we smuggle W,b after idb)
    // -- actual staging happens in the loop below --
    __syncthreads();
    // NOTE: W and bias pointers are passed through constant params Wg, Bg:
    // (declared below via additional parameters)
    // ==================================================================

    // unreachable marker (structure replaced by full kernel with W args)
    (void)S; (void)lane; (void)wid; (void)N; (void)out; (void)ida; (void)idb; (void)Bv;
}

// Real kernel (with W / bias parameters).
__global__ __launch_bounds__(NTHR, 1)
void fused_kernel(const float* __restrict__ A, const float* __restrict__ Bv,
                  const int* __restrict__ ida, const int* __restrict__ idb,
                  const float* __restrict__ Wg, const float* __restrict__ Bg,
                  int N, float* __restrict__ out)
{
    extern __shared__ char smemraw[];
    Smem* S = (Smem*)smemraw;
    const int tid = threadIdx.x, lane = tid & 31, wid = tid >> 5;

    // ---------- prologue phase 0: stage W / bias ----------
    for (int i = tid; i < 4 * 14 * 64; i += NTHR) S->Wst[i] = Wg[i];
    for (int i = tid; i < 4 * 64; i += NTHR)      S->Bst[i] = Bg[i];
    if (tid < 16) S->count[tid] = 0;
    __syncthreads();

    // ---------- prologue phase 1: Gram entries (all threads) ----------
    for (int t = tid; t < 16 * 406; t += NTHR) {
        int p = t / 406, e = t % 406;
        int j = (int)((sqrtf(8.f * e + 1.f) - 1.f) * 0.5f);
        while ((j + 1) * (j + 2) / 2 <= e) j++;
        while (j * (j + 1) / 2 > e) j--;
        int k = e - j * (j + 1) / 2;
        int ea = p >> 2, eb = p & 3;
        if (ea == eb && j >= 14) continue;
        const float* vj = S->Wst + ((j < 14) ? ea : eb) * 896 + ((j < 14) ? j : j - 14) * 64;
        const float* vk = S->Wst + ((k < 14) ? ea : eb) * 896 + ((k < 14) ? k : k - 14) * 64;
        float s = 0.f;
#pragma unroll 8
        for (int c = 0; c < 64; c++) s = fmaf(vj[c], vk[c], s);
        if ((j < 14) != (k < 14)) s = -s;
        S->C[p][j][k] = s;
    }
    for (int t = tid; t < 16 * 28 + 16; t += NTHR) {
        if (t < 16 * 28) {
            int p = t / 28, j = t % 28;
            int ea = p >> 2, eb = p & 3;
            if (ea == eb) continue;
            const float* vj = S->Wst + ((j < 14) ? ea : eb) * 896 + ((j < 14) ? j : j - 14) * 64;
            float s = 0.f;
#pragma unroll 8
            for (int c = 0; c < 64; c++)
                s = fmaf(vj[c], S->Bst[ea * 64 + c] - S->Bst[eb * 64 + c], s);
            S->Mc[p][j] = (j < 14) ? s : -s;
        } else {
            int p = t - 16 * 28;
            int ea = p >> 2, eb = p & 3;
            float s = 0.f;
            if (ea != eb)
                for (int c = 0; c < 64; c++) {
                    float d = S->Bst[ea * 64 + c] - S->Bst[eb * 64 + c];
                    s = fmaf(d, d, s);
                }
            S->cc[p] = s;
        }
    }
    __syncthreads();

    // ---------- prologue phase 2: per-warp Cholesky + solve + pack ----------
    {
        const int p = wid;           // 16 warps, one pair each
        float (*C)[29] = S->C[p];
        const int ea = p >> 2, eb = p & 3;
        const bool diag = (ea == eb);
        const int dim = diag ? 14 : 28;

        for (int k = 0; k < dim; k++) {
            float akk = C[k][k];
            __syncwarp();
            float sq = sqrtf(akk);
            float inv = 1.0f / sq;
            if (lane >= k && lane < dim) C[lane][k] = (lane == k) ? sq : C[lane][k] * inv;
            __syncwarp();
            if (lane > k && lane < dim) {
                float cjk = C[lane][k];
                for (int m = k + 1; m <= lane; m++) C[lane][m] -= cjk * C[m][k];
            }
            __syncwarp();
        }

        if (!diag) {
            float* dv = S->Mc[p];
            for (int k = 0; k < 28; k++) {
                if (lane == k) dv[k] = dv[k] / C[k][k];
                __syncwarp();
                if (lane > k && lane < 28) dv[lane] -= C[lane][k] * dv[k];
                __syncwarp();
            }
            float t = (lane < 28) ? dv[lane] * dv[lane] : 0.f;
#pragma unroll
            for (int off = 16; off; off >>= 1) t += __shfl_xor_sync(0xffffffffu, t, off);

            const int slot = p - p / 5 - 1;
            ull* T = S->tab + slot * OFF_ULL;
            if (lane == 0) ((float*)(S->tab + SPRIME_U))[p] = S->cc[p] - t;
            if (lane < 14) T[lane] = pk2(dv[2 * lane], dv[2 * lane + 1]);
            if (lane < 28) {
                int q = lane >> 1;
                ull* Tj = T + 14 + frow(lane);
                for (int kk = 0; kk <= q; kk++) {
                    float lo = C[lane][2 * kk];
                    float hi = (2 * kk + 1 <= lane) ? C[lane][2 * kk + 1] : 0.f;
                    Tj[kk] = pk2(lo, hi);
                }
            }
        } else {
            ull* T = S->tab + DIAG_BASE + (p / 5) * DIAG_ULL;
            if (lane == 0) ((float*)(S->tab + SPRIME_U))[p] = 0.f;
            if (lane < 14) {
                int q = lane >> 1;
                ull* Tj = T + frow(lane);
                for (int kk = 0; kk <= q; kk++) {
                    float lo = C[lane][2 * kk];
                    float hi = (2 * kk + 1 <= lane) ? C[lane][2 * kk + 1] : 0.f;
                    Tj[kk] = pk2(lo, hi);
                }
            }
        }
    }

    // ================= main loop =================
    const float* sS = (const float*)(S->tab + SPRIME_U);
    const ull* gA = (const ull*)A;
    const ull* gB = (const ull*)Bv;
    const ull neg1 = pk2(-1.f, -1.f);
    const int numTiles = (N + TILE - 1) / TILE;
    float acc = 0.f;

    for (int tile = blockIdx.x; tile < numTiles; tile += gridDim.x) {
        const int base = tile * TILE;
        const int cnt  = min(TILE, N - base);

        __syncthreads();                            // B4/B_top: prev compute done

        // histogram (2 rows/thread) + L2 prefetch of next tile
#pragma unroll
        for (int s = 0; s < 2; s++) {
            int r = tid + s * NTHR;
            if (r < cnt) {
                int p = __ldg(ida + base + r) * 4 + __ldg(idb + base + r);
                S->pairv[r] = p;
                atomicAdd(&S->count[p], 1);
            }
        }
        {
            int nxt = tile + gridDim.x;
            if (nxt < numTiles) {
                int ncnt = min(TILE, N - nxt * TILE);
                size_t nb = (size_t)nxt * TILE * 56;
                int off = tid * 128;
                if (off < ncnt * 56) {
                    asm volatile("prefetch.global.L2 [%0];" :: "l"((const char*)A  + nb + off));
                    asm volatile("prefetch.global.L2 [%0];" :: "l"((const char*)Bv + nb + off));
                }
            }
        }
        __syncthreads();                            // B1

        // warp 0: prefix scan -> offsets + 64-row work items
        if (wid == 0) {
            int n = (lane < 16) ? S->count[lane] : 0;
            int nit = (n + 63) >> 6;
            int xs = n, xi = nit;
#pragma unroll
            for (int d = 1; d < 32; d <<= 1) {
                int ys = __shfl_up_sync(0xffffffffu, xs, d);
                int yi = __shfl_up_sync(0xffffffffu, xi, d);
                if (lane >= d) { xs += ys; xi += yi; }
            }
            int rowS = xs - n, itS = xi - nit;
            if (lane < 16) {
                S->ofs[lane] = rowS;
                for (int f = 0; f < nit; f++) {
                    S->wP[itS + f] = lane;
                    S->wO[itS + f] = rowS + f * 64;
                    S->wN[itS + f] = min(64, n - f * 64);
                }
            }
            if (lane == 15) S->num = xi;
            if (lane == 0)  S->item = 0;
        }
        __syncthreads();                            // B2

        // scatter into pair-sorted order; clear counts for next tile
#pragma unroll
        for (int s = 0; s < 2; s++) {
            int r = tid + s * NTHR;
            if (r < cnt) {
                int pos = atomicAdd(&S->ofs[S->pairv[r]], 1);
                S->order[pos] = r;
            }
        }
        if (tid < 16) S->count[tid] = 0;
        __syncthreads();                            // B3

        // compute: dynamic item grab, rows direct from global
        const int nItems = S->num;
        int it;
        if (lane == 0) it = atomicAdd(&S->item, 1);
        it = __shfl_sync(0xffffffffu, it, 0);
        while (it < nItems) {
            const int pp = S->wP[it], off = S->wO[it], n = S->wN[it];
            const bool v1 = lane < n;
            const bool v2 = 32 + lane < n;
            const int r1 = S->order[off + (v1 ? lane : 0)];
            const int r2 = S->order[off + (v2 ? 32 + lane : 0)];
            const ull* A1 = gA + (size_t)(base + r1) * 7;
            const ull* B1 = gB + (size_t)(base + r1) * 7;
            const ull* A2 = gA + (size_t)(base + r2) * 7;
            const ull* B2 = gB + (size_t)(base + r2) * 7;
            if (pp % 5 == 0) {
                const ull* T = S->tab + DIAG_BASE + (pp / 5) * DIAG_ULL;
                acc += (n > 32) ? eval_diag<true >(T, A1, B1, A2, B2, v1, v2, neg1)
                                : eval_diag<false>(T, A1, B1, A1, B1, v1, false, neg1);
            } else {
                const int slot = pp - pp / 5 - 1;
                const ull* T = S->tab + slot * OFF_ULL;
                const float sp = sS[pp];
                acc += (n > 32) ? eval_off<true >(T, sp, A1, B1, A2, B2, v1, v2)
                                : eval_off<false>(T, sp, A1, B1, A1, B1, v1, false);
            }
            if (lane == 0) it = atomicAdd(&S->item, 1);
            it = __shfl_sync(0xffffffffu, it, 0);
        }
    }

    // ---------- reduction + finalize (last CTA writes out, resets globals) ----
    __syncthreads();
#pragma unroll
    for (int off = 16; off; off >>= 1) acc += __shfl_xor_sync(0xffffffffu, acc, off);
    if (lane == 0) S->red[wid] = acc;
    __syncthreads();
    if (wid == 0) {
        float v = (lane < NWARP) ? S->red[lane] : 0.f;
#pragma unroll
        for (int off = 16; off; off >>= 1) v += __shfl_xor_sync(0xffffffffu, v, off);
        if (lane == 0) {
            atomicAdd(&g_sum, (double)v);
            __threadfence();
            int done = atomicAdd(&g_done, 1);
            if (done == (int)gridDim.x - 1) {
                double s = *((volatile double*)&g_sum);
                out[0] = (float)(s / ((double)N * 64.0));
                g_sum = 0.0;                 // reset for next graph replay
                g_done = 0;
            }
        }
    }
}

// ---------------------------------------------------------------------------

extern "C" void kernel_launch(void* const* d_in, const int* in_sizes, int n_in,
                              void* d_out, int out_size) {
    const float* A    = (const float*)d_in[0];   // (N,14)
    const float* B    = (const float*)d_in[1];   // (N,14)
    const int*   ia   = (const int*)d_in[2];     // (N,)
    const int*   ib   = (const int*)d_in[3];     // (N,)
    const float* W    = (const float*)d_in[4];   // (4,14,64)
    const float* bias = (const float*)d_in[5];   // (4,64)
    const int N = in_sizes[0] / 14;

    size_t smemBytes = sizeof(Smem) + 64;
    cudaFuncSetAttribute(fused_kernel, cudaFuncAttributeMaxDynamicSharedMemorySize,
                         (int)smemBytes);

    int sms = 148;
    cudaDeviceGetAttribute(&sms, cudaDevAttrMultiProcessorCount, 0);
    int numTiles = (N + TILE - 1) / TILE;
    int grid = numTiles < sms ? numTiles : sms;

    fused_kernel<<<grid, NTHR, smemBytes>>>(A, B, ia, ib, W, bias, N, (float*)d_out);
}

// round 12
// speedup vs baseline: 1.0419x; 1.0419x over previous
#include <cuda_runtime.h>
#include <cstdint>

// ---------------------------------------------------------------------------
// FrameConsistencyLoss, single persistent kernel.
//
// Prologue (per CTA, redundant): stage W/bias in smem, 16 pair Gram matrices,
// per-warp Cholesky + solve + packed table (scratch aliases the tile buffers).
// Main loop: cp.async double-buffered 768-row tiles; histogram + counting
// sort by (ea,eb); warps grab pair-uniform 64-row fused items (one broadcast
// table stream feeds two row sets); rows read from staged smem.
//
// L_row(off-diag) = || C^T w + d ||^2 + s'   (w=[a;b], C = chol(M M^T))
// L_row(diag)     = || C14^T (a-b) ||^2
// ---------------------------------------------------------------------------

#define TILE   768
#define NTHR   512
#define NWARP  16
#define MAXW   28

// table layout in ULLs
#define OFF_ULL   224
#define DIAG_BASE 2688
#define DIAG_ULL  56
#define SPRIME_U  2912
#define TAB_U     2920

#define ROW_B     56                      // bytes per row (14 floats)
#define HALF_B    (TILE * ROW_B)          // one array (A or B) per slot
#define BUF_SLOT  (2 * HALF_B)            // A then B

typedef unsigned long long ull;

__device__ double g_sum;
__device__ int    g_done;

__device__ __forceinline__ ull pk2(float lo, float hi) {
    ull r; asm("mov.b64 %0, {%1,%2};" : "=l"(r) : "f"(lo), "f"(hi)); return r;
}
__device__ __forceinline__ void upk2(ull v, float& lo, float& hi) {
    asm("mov.b64 {%0,%1}, %2;" : "=f"(lo), "=f"(hi) : "l"(v));
}
__device__ __forceinline__ ull ffma2(ull a, ull b, ull c) {
    ull d; asm("fma.rn.f32x2 %0, %1, %2, %3;" : "=l"(d) : "l"(a), "l"(b), "l"(c)); return d;
}
__device__ __forceinline__ uint32_t smem_u32(const void* p) {
    uint32_t a;
    asm("{ .reg .u64 t; cvta.to.shared.u64 t, %1; cvt.u32.u64 %0, t; }" : "=r"(a) : "l"(p));
    return a;
}
__device__ __forceinline__ void cp16(uint32_t s, const void* g) {
    asm volatile("cp.async.cg.shared.global [%0], [%1], 16;" :: "r"(s), "l"(g));
}
__device__ __forceinline__ void cp8(uint32_t s, const void* g) {
    asm volatile("cp.async.ca.shared.global [%0], [%1], 8;" :: "r"(s), "l"(g));
}

__device__ __forceinline__ int frow(int j) {       // ulls in C-rows 0..j-1
    int q = j >> 1, r = j & 1;
    return j + q * (q - 1) + r * q;
}

struct Smem {
    ull tab[TAB_U];
    union {
        struct {
            float C[16][28][29];
            float Mc[16][28];
            float cc[16];
            float Wst[4 * 14 * 64];
            float Bst[4 * 64];
        } pro;
        char buf[2][BUF_SLOT];
    } u;
    int   order[TILE];
    int   count[16];
    int   ofs[16];
    int   wP[MAXW], wO[MAXW], wN[MAXW];
    int   num, item;
    float red[NWARP];
};

// ---------------------------------------------------------------------------
// evaluation (pack-over-k; fused variant shares table LDS across 2 row sets)
// ---------------------------------------------------------------------------
template<bool FUSED>
__device__ __forceinline__ float eval_off(const ull* __restrict__ T, float sp,
    const ull* __restrict__ A1, const ull* __restrict__ B1,
    const ull* __restrict__ A2, const ull* __restrict__ B2,
    bool v1, bool v2)
{
    ull S1[14], S2[14];
#pragma unroll
    for (int k = 0; k < 14; k++) { S1[k] = T[k]; if (FUSED) S2[k] = T[k]; }
    int idx = 14;
#pragma unroll
    for (int jj = 0; jj < 14; jj++) {
        ull w1 = (jj < 7) ? A1[jj] : B1[jj - 7];
        float lo1, hi1; upk2(w1, lo1, hi1);
        ull bl1 = pk2(lo1, lo1), bh1 = pk2(hi1, hi1);
        ull bl2 = 0, bh2 = 0;
        if (FUSED) {
            ull w2 = (jj < 7) ? A2[jj] : B2[jj - 7];
            float lo2, hi2; upk2(w2, lo2, hi2);
            bl2 = pk2(lo2, lo2); bh2 = pk2(hi2, hi2);
        }
#pragma unroll
        for (int kk = 0; kk <= jj; kk++) {
            ull t = T[idx + kk];
            S1[kk] = ffma2(t, bl1, S1[kk]);
            if (FUSED) S2[kk] = ffma2(t, bl2, S2[kk]);
        }
#pragma unroll
        for (int kk = 0; kk <= jj; kk++) {
            ull t = T[idx + jj + 1 + kk];
            S1[kk] = ffma2(t, bh1, S1[kk]);
            if (FUSED) S2[kk] = ffma2(t, bh2, S2[kk]);
        }
        idx += 2 * (jj + 1);
    }
    float L1 = sp, L2 = sp;
#pragma unroll
    for (int k = 0; k < 14; k++) {
        float lo, hi;
        upk2(S1[k], lo, hi); L1 = fmaf(lo, lo, L1); L1 = fmaf(hi, hi, L1);
        if (FUSED) { upk2(S2[k], lo, hi); L2 = fmaf(lo, lo, L2); L2 = fmaf(hi, hi, L2); }
    }
    float r = v1 ? L1 : 0.f;
    if (FUSED) r += v2 ? L2 : 0.f;
    return r;
}

template<bool FUSED>
__device__ __forceinline__ float eval_diag(const ull* __restrict__ T,
    const ull* __restrict__ A1, const ull* __restrict__ B1,
    const ull* __restrict__ A2, const ull* __restrict__ B2,
    bool v1, bool v2, ull neg1)
{
    ull u1[7], u2[7];
#pragma unroll
    for (int j = 0; j < 7; j++) {
        u1[j] = ffma2(B1[j], neg1, A1[j]);
        if (FUSED) u2[j] = ffma2(B2[j], neg1, A2[j]);
    }
    ull S1[7], S2[7];
    const ull z = pk2(0.f, 0.f);
#pragma unroll
    for (int k = 0; k < 7; k++) { S1[k] = z; if (FUSED) S2[k] = z; }
    int idx = 0;
#pragma unroll
    for (int jj = 0; jj < 7; jj++) {
        float lo1, hi1; upk2(u1[jj], lo1, hi1);
        ull bl1 = pk2(lo1, lo1), bh1 = pk2(hi1, hi1);
        ull bl2 = 0, bh2 = 0;
        if (FUSED) {
            float lo2, hi2; upk2(u2[jj], lo2, hi2);
            bl2 = pk2(lo2, lo2); bh2 = pk2(hi2, hi2);
        }
#pragma unroll
        for (int kk = 0; kk <= jj; kk++) {
            ull t = T[idx + kk];
            S1[kk] = ffma2(t, bl1, S1[kk]);
            if (FUSED) S2[kk] = ffma2(t, bl2, S2[kk]);
        }
#pragma unroll
        for (int kk = 0; kk <= jj; kk++) {
            ull t = T[idx + jj + 1 + kk];
            S1[kk] = ffma2(t, bh1, S1[kk]);
            if (FUSED) S2[kk] = ffma2(t, bh2, S2[kk]);
        }
        idx += 2 * (jj + 1);
    }
    float L1 = 0.f, L2 = 0.f;
#pragma unroll
    for (int k = 0; k < 7; k++) {
        float lo, hi;
        upk2(S1[k], lo, hi); L1 = fmaf(lo, lo, L1); L1 = fmaf(hi, hi, L1);
        if (FUSED) { upk2(S2[k], lo, hi); L2 = fmaf(lo, lo, L2); L2 = fmaf(hi, hi, L2); }
    }
    float r = v1 ? L1 : 0.f;
    if (FUSED) r += v2 ? L2 : 0.f;
    return r;
}

// ---------------------------------------------------------------------------

__device__ __forceinline__ void stage(uint32_t dstA, uint32_t dstB,
        const char* gA, const char* gB, int bytes, int tid) {
    const int n16 = bytes >> 4;
    for (int i = tid; i < n16; i += NTHR) {
        cp16(dstA + (i << 4), gA + ((size_t)i << 4));
        cp16(dstB + (i << 4), gB + ((size_t)i << 4));
    }
    if ((bytes & 8) && tid == 0) {
        cp8(dstA + (n16 << 4), gA + ((size_t)n16 << 4));
        cp8(dstB + (n16 << 4), gB + ((size_t)n16 << 4));
    }
}

__global__ __launch_bounds__(NTHR, 1)
void fused_kernel(const float* __restrict__ A, const float* __restrict__ Bv,
                  const int* __restrict__ ida, const int* __restrict__ idb,
                  const float* __restrict__ Wg, const float* __restrict__ Bg,
                  int N, float* __restrict__ out)
{
    extern __shared__ char smemraw[];
    Smem* S = (Smem*)smemraw;
    const int tid = threadIdx.x, lane = tid & 31, wid = tid >> 5;
    const uint32_t smem_u = smem_u32(smemraw);
    const uint32_t buf_u  = smem_u + (uint32_t)offsetof(Smem, u);

    // ========== prologue phase 0: stage W / bias ==========
    for (int i = tid; i < 4 * 14 * 64; i += NTHR) S->u.pro.Wst[i] = Wg[i];
    for (int i = tid; i < 4 * 64; i += NTHR)      S->u.pro.Bst[i] = Bg[i];
    if (tid < 16) S->count[tid] = 0;
    __syncthreads();

    // ========== prologue phase 1: Gram entries ==========
    for (int t = tid; t < 16 * 406; t += NTHR) {
        int p = t / 406, e = t % 406;
        int j = (int)((sqrtf(8.f * e + 1.f) - 1.f) * 0.5f);
        while ((j + 1) * (j + 2) / 2 <= e) j++;
        while (j * (j + 1) / 2 > e) j--;
        int k = e - j * (j + 1) / 2;
        int ea = p >> 2, eb = p & 3;
        if (ea == eb && j >= 14) continue;
        const float* vj = S->u.pro.Wst + ((j < 14) ? ea : eb) * 896 + ((j < 14) ? j : j - 14) * 64;
        const float* vk = S->u.pro.Wst + ((k < 14) ? ea : eb) * 896 + ((k < 14) ? k : k - 14) * 64;
        float s = 0.f;
#pragma unroll 8
        for (int c = 0; c < 64; c++) s = fmaf(vj[c], vk[c], s);
        if ((j < 14) != (k < 14)) s = -s;
        S->u.pro.C[p][j][k] = s;
    }
    for (int t = tid; t < 16 * 28 + 16; t += NTHR) {
        if (t < 16 * 28) {
            int p = t / 28, j = t % 28;
            int ea = p >> 2, eb = p & 3;
            if (ea == eb) continue;
            const float* vj = S->u.pro.Wst + ((j < 14) ? ea : eb) * 896 + ((j < 14) ? j : j - 14) * 64;
            float s = 0.f;
#pragma unroll 8
            for (int c = 0; c < 64; c++)
                s = fmaf(vj[c], S->u.pro.Bst[ea * 64 + c] - S->u.pro.Bst[eb * 64 + c], s);
            S->u.pro.Mc[p][j] = (j < 14) ? s : -s;
        } else {
            int p = t - 16 * 28;
            int ea = p >> 2, eb = p & 3;
            float s = 0.f;
            if (ea != eb)
                for (int c = 0; c < 64; c++) {
                    float d = S->u.pro.Bst[ea * 64 + c] - S->u.pro.Bst[eb * 64 + c];
                    s = fmaf(d, d, s);
                }
            S->u.pro.cc[p] = s;
        }
    }
    __syncthreads();

    // ========== prologue phase 2: per-warp Cholesky + solve + pack ==========
    {
        const int p = wid;
        float (*C)[29] = S->u.pro.C[p];
        const int ea = p >> 2, eb = p & 3;
        const bool diag = (ea == eb);
        const int dim = diag ? 14 : 28;

        for (int k = 0; k < dim; k++) {
            float akk = C[k][k];
            __syncwarp();
            float sq = sqrtf(akk);
            float inv = 1.0f / sq;
            if (lane >= k && lane < dim) C[lane][k] = (lane == k) ? sq : C[lane][k] * inv;
            __syncwarp();
            if (lane > k && lane < dim) {
                float cjk = C[lane][k];
                for (int m = k + 1; m <= lane; m++) C[lane][m] -= cjk * C[m][k];
            }
            __syncwarp();
        }

        if (!diag) {
            float* dv = S->u.pro.Mc[p];
            for (int k = 0; k < 28; k++) {
                if (lane == k) dv[k] = dv[k] / C[k][k];
                __syncwarp();
                if (lane > k && lane < 28) dv[lane] -= C[lane][k] * dv[k];
                __syncwarp();
            }
            float t = (lane < 28) ? dv[lane] * dv[lane] : 0.f;
#pragma unroll
            for (int off = 16; off; off >>= 1) t += __shfl_xor_sync(0xffffffffu, t, off);

            const int slot = p - p / 5 - 1;
            ull* T = S->tab + slot * OFF_ULL;
            if (lane == 0) ((float*)(S->tab + SPRIME_U))[p] = S->u.pro.cc[p] - t;
            if (lane < 14) T[lane] = pk2(dv[2 * lane], dv[2 * lane + 1]);
            if (lane < 28) {
                int q = lane >> 1;
                ull* Tj = T + 14 + frow(lane);
                for (int kk = 0; kk <= q; kk++) {
                    float lo = C[lane][2 * kk];
                    float hi = (2 * kk + 1 <= lane) ? C[lane][2 * kk + 1] : 0.f;
                    Tj[kk] = pk2(lo, hi);
                }
            }
        } else {
            ull* T = S->tab + DIAG_BASE + (p / 5) * DIAG_ULL;
            if (lane == 0) ((float*)(S->tab + SPRIME_U))[p] = 0.f;
            if (lane < 14) {
                int q = lane >> 1;
                ull* Tj = T + frow(lane);
                for (int kk = 0; kk <= q; kk++) {
                    float lo = C[lane][2 * kk];
                    float hi = (2 * kk + 1 <= lane) ? C[lane][2 * kk + 1] : 0.f;
                    Tj[kk] = pk2(lo, hi);
                }
            }
        }
    }
    __syncthreads();              // prologue scratch dead; buffers may now be written

    // ========== main loop: double-buffered pipeline ==========
    const float* sS = (const float*)(S->tab + SPRIME_U);
    const ull neg1 = pk2(-1.f, -1.f);
    const int numTiles = (N + TILE - 1) / TILE;
    float acc = 0.f;
    int cur = 0;

    // prologue staging of first tile + its ids
    if (blockIdx.x < numTiles) {
        int cnt = min(TILE, N - blockIdx.x * TILE);
        stage(buf_u, buf_u + HALF_B,
              (const char*)A  + (size_t)blockIdx.x * TILE * ROW_B,
              (const char*)Bv + (size_t)blockIdx.x * TILE * ROW_B, cnt * ROW_B, tid);
    }
    asm volatile("cp.async.commit_group;");
    int cp0 = 0, cp1 = 0;
    if (blockIdx.x < numTiles) {
        int g0 = blockIdx.x * TILE + tid;
        int g1 = g0 + NTHR;
        if (g0 < N) cp0 = __ldg(ida + g0) * 4 + __ldg(idb + g0);
        if (g1 < N && tid + NTHR < TILE) cp1 = __ldg(ida + g1) * 4 + __ldg(idb + g1);
    }

    for (int tile = blockIdx.x; tile < numTiles; tile += gridDim.x) {
        const int cnt = min(TILE, N - tile * TILE);
        asm volatile("cp.async.wait_group 0;");
        __syncthreads();                                  // buffer ready, prev compute done

        // kick off next tile's copy into the other buffer
        const int nxt = tile + gridDim.x;
        const int nb = cur ^ 1;
        if (nxt < numTiles) {
            int ncnt = min(TILE, N - nxt * TILE);
            stage(buf_u + nb * BUF_SLOT, buf_u + nb * BUF_SLOT + HALF_B,
                  (const char*)A  + (size_t)nxt * TILE * ROW_B,
                  (const char*)Bv + (size_t)nxt * TILE * ROW_B, ncnt * ROW_B, tid);
        }
        asm volatile("cp.async.commit_group;");

        // histogram (ids already in regs)
        const bool act0 = tid < cnt;
        const bool act1 = tid + NTHR < cnt;
        if (act0) atomicAdd(&S->count[cp0], 1);
        if (act1) atomicAdd(&S->count[cp1], 1);

        // prefetch next tile's ids
        int np0 = 0, np1 = 0;
        if (nxt < numTiles) {
            int g0 = nxt * TILE + tid;
            int g1 = g0 + NTHR;
            if (g0 < N) np0 = __ldg(ida + g0) * 4 + __ldg(idb + g0);
            if (g1 < N && tid + NTHR < TILE) np1 = __ldg(ida + g1) * 4 + __ldg(idb + g1);
        }
        __syncthreads();

        // warp 0: prefix scan -> offsets + 64-row work items
        if (wid == 0) {
            int n = (lane < 16) ? S->count[lane] : 0;
            int nit = (n + 63) >> 6;
            int xs = n, xi = nit;
#pragma unroll
            for (int d = 1; d < 32; d <<= 1) {
                int ys = __shfl_up_sync(0xffffffffu, xs, d);
                int yi = __shfl_up_sync(0xffffffffu, xi, d);
                if (lane >= d) { xs += ys; xi += yi; }
            }
            int rowS = xs - n, itS = xi - nit;
            if (lane < 16) {
                S->ofs[lane] = rowS;
                for (int f = 0; f < nit; f++) {
                    S->wP[itS + f] = lane;
                    S->wO[itS + f] = rowS + f * 64;
                    S->wN[itS + f] = min(64, n - f * 64);
                }
            }
            if (lane == 15) S->num = xi;
            if (lane == 0)  S->item = 0;
        }
        __syncthreads();

        // scatter; clear counts for next tile
        if (act0) { int pos = atomicAdd(&S->ofs[cp0], 1); S->order[pos] = tid; }
        if (act1) { int pos = atomicAdd(&S->ofs[cp1], 1); S->order[pos] = tid + NTHR; }
        if (tid < 16) S->count[tid] = 0;
        __syncthreads();

        // compute: dynamic item grab, rows from staged smem
        const ull* bufA = (const ull*)(S->u.buf[cur]);
        const ull* bufB = bufA + TILE * 7;
        const int nItems = S->num;
        int it;
        if (lane == 0) it = atomicAdd(&S->item, 1);
        it = __shfl_sync(0xffffffffu, it, 0);
        while (it < nItems) {
            const int pp = S->wP[it], off = S->wO[it], n = S->wN[it];
            const bool v1 = lane < n;
            const bool v2 = 32 + lane < n;
            const int r1 = S->order[off + (v1 ? lane : 0)];
            const int r2 = S->order[off + (v2 ? 32 + lane : 0)];
            const ull* A1 = bufA + r1 * 7; const ull* B1 = bufB + r1 * 7;
            const ull* A2 = bufA + r2 * 7; const ull* B2 = bufB + r2 * 7;
            if (pp % 5 == 0) {
                const ull* T = S->tab + DIAG_BASE + (pp / 5) * DIAG_ULL;
                acc += (n > 32) ? eval_diag<true >(T, A1, B1, A2, B2, v1, v2, neg1)
                                : eval_diag<false>(T, A1, B1, A1, B1, v1, false, neg1);
            } else {
                const int slot = pp - pp / 5 - 1;
                const ull* T = S->tab + slot * OFF_ULL;
                const float sp = sS[pp];
                acc += (n > 32) ? eval_off<true >(T, sp, A1, B1, A2, B2, v1, v2)
                                : eval_off<false>(T, sp, A1, B1, A1, B1, v1, false);
            }
            if (lane == 0) it = atomicAdd(&S->item, 1);
            it = __shfl_sync(0xffffffffu, it, 0);
        }
        cp0 = np0; cp1 = np1; cur ^= 1;
    }

    // ---------- reduction + finalize (last CTA writes out, resets globals) ----
    __syncthreads();
#pragma unroll
    for (int off = 16; off; off >>= 1) acc += __shfl_xor_sync(0xffffffffu, acc, off);
    if (lane == 0) S->red[wid] = acc;
    __syncthreads();
    if (wid == 0) {
        float v = (lane < NWARP) ? S->red[lane] : 0.f;
#pragma unroll
        for (int off = 16; off; off >>= 1) v += __shfl_xor_sync(0xffffffffu, v, off);
        if (lane == 0) {
            atomicAdd(&g_sum, (double)v);
            __threadfence();
            int done = atomicAdd(&g_done, 1);
            if (done == (int)gridDim.x - 1) {
                double s = *((volatile double*)&g_sum);
                out[0] = (float)(s / ((double)N * 64.0));
                g_sum = 0.0;                 // reset for next graph replay
                g_done = 0;
            }
        }
    }
}

// ---------------------------------------------------------------------------

extern "C" void kernel_launch(void* const* d_in, const int* in_sizes, int n_in,
                              void* d_out, int out_size) {
    const float* A    = (const float*)d_in[0];   // (N,14)
    const float* B    = (const float*)d_in[1];   // (N,14)
    const int*   ia   = (const int*)d_in[2];     // (N,)
    const int*   ib   = (const int*)d_in[3];     // (N,)
    const float* W    = (const float*)d_in[4];   // (4,14,64)
    const float* bias = (const float*)d_in[5];   // (4,64)
    const int N = in_sizes[0] / 14;

    size_t smemBytes = sizeof(Smem) + 64;
    cudaFuncSetAttribute(fused_kernel, cudaFuncAttributeMaxDynamicSharedMemorySize,
                         (int)smemBytes);

    int sms = 148;
    cudaDeviceGetAttribute(&sms, cudaDevAttrMultiProcessorCount, 0);
    int numTiles = (N + TILE - 1) / TILE;
    int grid = numTiles < sms ? numTiles : sms;

    fused_kernel<<<grid, NTHR, smemBytes>>>(A, B, ia, ib, W, bias, N, (float*)d_out);
}

// round 13
// speedup vs baseline: 1.3205x; 1.2673x over previous
#include <cuda_runtime.h>
#include <cstdint>

// ---------------------------------------------------------------------------
// FrameConsistencyLoss, single persistent kernel.
//
// Prologue (per CTA, redundant, conflict-free): stage W (row-padded, stride
// 65) + bias; 10 expert-level Grams G(x,y)=W_x W_y^T; assemble 16 pair
// matrices M M^T from G blocks; per-warp Cholesky + solve + packed table.
// Main loop: cp.async double-buffered 768-row tiles; histogram + counting
// sort by (ea,eb); warps grab pair-uniform 64-row fused items (one broadcast
// table stream feeds two row sets); rows read from staged smem.
//
// L_row(off-diag) = || C^T w + d ||^2 + s'   (w=[a;b], C = chol(M M^T))
// L_row(diag)     = || C14^T (a-b) ||^2
// ---------------------------------------------------------------------------

#define TILE   768
#define NTHR   512
#define NWARP  16
#define MAXW   28

// table layout in ULLs
#define OFF_ULL   224
#define DIAG_BASE 2688
#define DIAG_ULL  56
#define SPRIME_U  2912
#define TAB_U     2920

#define ROW_B     56                      // bytes per row (14 floats)
#define HALF_B    (TILE * ROW_B)          // one array (A or B) per slot
#define BUF_SLOT  (2 * HALF_B)            // A then B

typedef unsigned long long ull;

__device__ double g_sum;
__device__ int    g_done;

__device__ const int PX[10] = {0,0,0,0,1,1,1,2,2,3};
__device__ const int PY[10] = {0,1,2,3,1,2,3,2,3,3};

__device__ __forceinline__ int qidx(int x, int y) {   // x <= y
    return 4 * x - (x * (x - 1)) / 2 + (y - x);
}

__device__ __forceinline__ ull pk2(float lo, float hi) {
    ull r; asm("mov.b64 %0, {%1,%2};" : "=l"(r) : "f"(lo), "f"(hi)); return r;
}
__device__ __forceinline__ void upk2(ull v, float& lo, float& hi) {
    asm("mov.b64 {%0,%1}, %2;" : "=f"(lo), "=f"(hi) : "l"(v));
}
__device__ __forceinline__ ull ffma2(ull a, ull b, ull c) {
    ull d; asm("fma.rn.f32x2 %0, %1, %2, %3;" : "=l"(d) : "l"(a), "l"(b), "l"(c)); return d;
}
__device__ __forceinline__ uint32_t smem_u32(const void* p) {
    uint32_t a;
    asm("{ .reg .u64 t; cvta.to.shared.u64 t, %1; cvt.u32.u64 %0, t; }" : "=r"(a) : "l"(p));
    return a;
}
__device__ __forceinline__ void cp16(uint32_t s, const void* g) {
    asm volatile("cp.async.cg.shared.global [%0], [%1], 16;" :: "r"(s), "l"(g));
}
__device__ __forceinline__ void cp8(uint32_t s, const void* g) {
    asm volatile("cp.async.ca.shared.global [%0], [%1], 8;" :: "r"(s), "l"(g));
}

__device__ __forceinline__ int frow(int j) {       // ulls in C-rows 0..j-1
    int q = j >> 1, r = j & 1;
    return j + q * (q - 1) + r * q;
}

struct Pro {
    float Wst[56 * 65];        // W rows, stride 65 (bank-conflict-free)
    float Bst[4 * 64];
    float Ge[10 * 14 * 15];    // expert Grams, row stride 15
    float C[16][28][29];       // assembled M M^T -> Cholesky scratch
    float Mc[16][28];
    float cc[16];
};

struct Smem {
    ull tab[TAB_U];
    union {
        Pro  pro;
        char buf[2][BUF_SLOT];
    } u;
    int   order[TILE];
    int   count[16];
    int   ofs[16];
    int   wP[MAXW], wO[MAXW], wN[MAXW];
    int   num, item;
    float red[NWARP];
};

// ---------------------------------------------------------------------------
// evaluation (pack-over-k; fused variant shares table LDS across 2 row sets)
// ---------------------------------------------------------------------------
template<bool FUSED>
__device__ __forceinline__ float eval_off(const ull* __restrict__ T, float sp,
    const ull* __restrict__ A1, const ull* __restrict__ B1,
    const ull* __restrict__ A2, const ull* __restrict__ B2,
    bool v1, bool v2)
{
    ull S1[14], S2[14];
#pragma unroll
    for (int k = 0; k < 14; k++) { S1[k] = T[k]; if (FUSED) S2[k] = T[k]; }
    int idx = 14;
#pragma unroll
    for (int jj = 0; jj < 14; jj++) {
        ull w1 = (jj < 7) ? A1[jj] : B1[jj - 7];
        float lo1, hi1; upk2(w1, lo1, hi1);
        ull bl1 = pk2(lo1, lo1), bh1 = pk2(hi1, hi1);
        ull bl2 = 0, bh2 = 0;
        if (FUSED) {
            ull w2 = (jj < 7) ? A2[jj] : B2[jj - 7];
            float lo2, hi2; upk2(w2, lo2, hi2);
            bl2 = pk2(lo2, lo2); bh2 = pk2(hi2, hi2);
        }
#pragma unroll
        for (int kk = 0; kk <= jj; kk++) {
            ull t = T[idx + kk];
            S1[kk] = ffma2(t, bl1, S1[kk]);
            if (FUSED) S2[kk] = ffma2(t, bl2, S2[kk]);
        }
#pragma unroll
        for (int kk = 0; kk <= jj; kk++) {
            ull t = T[idx + jj + 1 + kk];
            S1[kk] = ffma2(t, bh1, S1[kk]);
            if (FUSED) S2[kk] = ffma2(t, bh2, S2[kk]);
        }
        idx += 2 * (jj + 1);
    }
    float L1 = sp, L2 = sp;
#pragma unroll
    for (int k = 0; k < 14; k++) {
        float lo, hi;
        upk2(S1[k], lo, hi); L1 = fmaf(lo, lo, L1); L1 = fmaf(hi, hi, L1);
        if (FUSED) { upk2(S2[k], lo, hi); L2 = fmaf(lo, lo, L2); L2 = fmaf(hi, hi, L2); }
    }
    float r = v1 ? L1 : 0.f;
    if (FUSED) r += v2 ? L2 : 0.f;
    return r;
}

template<bool FUSED>
__device__ __forceinline__ float eval_diag(const ull* __restrict__ T,
    const ull* __restrict__ A1, const ull* __restrict__ B1,
    const ull* __restrict__ A2, const ull* __restrict__ B2,
    bool v1, bool v2, ull neg1)
{
    ull u1[7], u2[7];
#pragma unroll
    for (int j = 0; j < 7; j++) {
        u1[j] = ffma2(B1[j], neg1, A1[j]);
        if (FUSED) u2[j] = ffma2(B2[j], neg1, A2[j]);
    }
    ull S1[7], S2[7];
    const ull z = pk2(0.f, 0.f);
#pragma unroll
    for (int k = 0; k < 7; k++) { S1[k] = z; if (FUSED) S2[k] = z; }
    int idx = 0;
#pragma unroll
    for (int jj = 0; jj < 7; jj++) {
        float lo1, hi1; upk2(u1[jj], lo1, hi1);
        ull bl1 = pk2(lo1, lo1), bh1 = pk2(hi1, hi1);
        ull bl2 = 0, bh2 = 0;
        if (FUSED) {
            float lo2, hi2; upk2(u2[jj], lo2, hi2);
            bl2 = pk2(lo2, lo2); bh2 = pk2(hi2, hi2);
        }
#pragma unroll
        for (int kk = 0; kk <= jj; kk++) {
            ull t = T[idx + kk];
            S1[kk] = ffma2(t, bl1, S1[kk]);
            if (FUSED) S2[kk] = ffma2(t, bl2, S2[kk]);
        }
#pragma unroll
        for (int kk = 0; kk <= jj; kk++) {
            ull t = T[idx + jj + 1 + kk];
            S1[kk] = ffma2(t, bh1, S1[kk]);
            if (FUSED) S2[kk] = ffma2(t, bh2, S2[kk]);
        }
        idx += 2 * (jj + 1);
    }
    float L1 = 0.f, L2 = 0.f;
#pragma unroll
    for (int k = 0; k < 7; k++) {
        float lo, hi;
        upk2(S1[k], lo, hi); L1 = fmaf(lo, lo, L1); L1 = fmaf(hi, hi, L1);
        if (FUSED) { upk2(S2[k], lo, hi); L2 = fmaf(lo, lo, L2); L2 = fmaf(hi, hi, L2); }
    }
    float r = v1 ? L1 : 0.f;
    if (FUSED) r += v2 ? L2 : 0.f;
    return r;
}

// ---------------------------------------------------------------------------

__device__ __forceinline__ void stage(uint32_t dstA, uint32_t dstB,
        const char* gA, const char* gB, int bytes, int tid) {
    const int n16 = bytes >> 4;
    for (int i = tid; i < n16; i += NTHR) {
        cp16(dstA + (i << 4), gA + ((size_t)i << 4));
        cp16(dstB + (i << 4), gB + ((size_t)i << 4));
    }
    if ((bytes & 8) && tid == 0) {
        cp8(dstA + (n16 << 4), gA + ((size_t)n16 << 4));
        cp8(dstB + (n16 << 4), gB + ((size_t)n16 << 4));
    }
}

__global__ __launch_bounds__(NTHR, 1)
void fused_kernel(const float* __restrict__ A, const float* __restrict__ Bv,
                  const int* __restrict__ ida, const int* __restrict__ idb,
                  const float* __restrict__ Wg, const float* __restrict__ Bg,
                  int N, float* __restrict__ out)
{
    extern __shared__ char smemraw[];
    Smem* S = (Smem*)smemraw;
    Pro*  P = &S->u.pro;
    const int tid = threadIdx.x, lane = tid & 31, wid = tid >> 5;
    const uint32_t smem_u = smem_u32(smemraw);
    const uint32_t buf_u  = smem_u + (uint32_t)offsetof(Smem, u);

    // ========== prologue phase 0: stage W (padded stride 65) / bias ==========
    for (int i = tid; i < 56 * 64; i += NTHR) {
        int r = i >> 6, c = i & 63;
        P->Wst[r * 65 + c] = Wg[i];
    }
    for (int i = tid; i < 4 * 64; i += NTHR) P->Bst[i] = Bg[i];
    if (tid < 16) S->count[tid] = 0;
    __syncthreads();

    // ========== phase 1: 10 expert Grams + Mc + cc (conflict-free) ==========
    for (int t = tid; t < 1960; t += NTHR) {
        int q = t / 196, r = t % 196, j = r / 14, k = r % 14;
        const float* vj = P->Wst + (PX[q] * 14 + j) * 65;
        const float* vk = P->Wst + (PY[q] * 14 + k) * 65;
        float s = 0.f;
#pragma unroll 8
        for (int c = 0; c < 64; c++) s = fmaf(vj[c], vk[c], s);
        P->Ge[q * 210 + j * 15 + k] = s;
    }
    for (int t = tid; t < 16 * 28 + 16; t += NTHR) {
        if (t < 16 * 28) {
            int p = t / 28, j = t % 28;
            int ea = p >> 2, eb = p & 3;
            if (ea == eb) continue;
            const float* vj = P->Wst + (((j < 14) ? ea : eb) * 14 + ((j < 14) ? j : j - 14)) * 65;
            const float* ba = P->Bst + ea * 64;
            const float* bb = P->Bst + eb * 64;
            float s = 0.f;
#pragma unroll 8
            for (int c = 0; c < 64; c++) s = fmaf(vj[c], ba[c] - bb[c], s);
            P->Mc[p][j] = (j < 14) ? s : -s;
        } else {
            int p = t - 16 * 28;
            int ea = p >> 2, eb = p & 3;
            float s = 0.f;
            if (ea != eb) {
                const float* ba = P->Bst + ea * 64;
                const float* bb = P->Bst + eb * 64;
                for (int c = 0; c < 64; c++) {
                    float d = ba[c] - bb[c];
                    s = fmaf(d, d, s);
                }
            }
            P->cc[p] = s;
        }
    }
    __syncthreads();

    // ========== phase 2: assemble pair matrices from expert Gram blocks ======
    for (int t = tid; t < 16 * 406; t += NTHR) {
        int p = t / 406, e = t % 406;
        int j = (int)((sqrtf(8.f * e + 1.f) - 1.f) * 0.5f);
        while ((j + 1) * (j + 2) / 2 <= e) j++;
        while (j * (j + 1) / 2 > e) j--;
        int k = e - j * (j + 1) / 2;
        int ea = p >> 2, eb = p & 3;
        if (ea == eb && j >= 14) continue;
        int xj = (j < 14) ? ea : eb, jj = (j < 14) ? j : j - 14;
        int xk = (k < 14) ? ea : eb, kk = (k < 14) ? k : k - 14;
        float v;
        if (xj <= xk) v = P->Ge[qidx(xj, xk) * 210 + jj * 15 + kk];
        else          v = P->Ge[qidx(xk, xj) * 210 + kk * 15 + jj];
        if ((j < 14) != (k < 14)) v = -v;
        P->C[p][j][k] = v;
    }
    __syncthreads();

    // ========== phase 3: per-warp Cholesky + solve + pack ==========
    {
        const int p = wid;
        float (*C)[29] = P->C[p];
        const int ea = p >> 2, eb = p & 3;
        const bool diag = (ea == eb);
        const int dim = diag ? 14 : 28;

        for (int k = 0; k < dim; k++) {
            float akk = C[k][k];
            __syncwarp();
            float sq = sqrtf(akk);
            float inv = 1.0f / sq;
            if (lane >= k && lane < dim) C[lane][k] = (lane == k) ? sq : C[lane][k] * inv;
            __syncwarp();
            if (lane > k && lane < dim) {
                float cjk = C[lane][k];
                for (int m = k + 1; m <= lane; m++) C[lane][m] -= cjk * C[m][k];
            }
            __syncwarp();
        }

        if (!diag) {
            float* dv = P->Mc[p];
            for (int k = 0; k < 28; k++) {
                if (lane == k) dv[k] = dv[k] / C[k][k];
                __syncwarp();
                if (lane > k && lane < 28) dv[lane] -= C[lane][k] * dv[k];
                __syncwarp();
            }
            float t = (lane < 28) ? dv[lane] * dv[lane] : 0.f;
#pragma unroll
            for (int off = 16; off; off >>= 1) t += __shfl_xor_sync(0xffffffffu, t, off);

            const int slot = p - p / 5 - 1;
            ull* T = S->tab + slot * OFF_ULL;
            if (lane == 0) ((float*)(S->tab + SPRIME_U))[p] = P->cc[p] - t;
            if (lane < 14) T[lane] = pk2(dv[2 * lane], dv[2 * lane + 1]);
            if (lane < 28) {
                int q = lane >> 1;
                ull* Tj = T + 14 + frow(lane);
                for (int kk2 = 0; kk2 <= q; kk2++) {
                    float lo = C[lane][2 * kk2];
                    float hi = (2 * kk2 + 1 <= lane) ? C[lane][2 * kk2 + 1] : 0.f;
                    Tj[kk2] = pk2(lo, hi);
                }
            }
        } else {
            ull* T = S->tab + DIAG_BASE + (p / 5) * DIAG_ULL;
            if (lane == 0) ((float*)(S->tab + SPRIME_U))[p] = 0.f;
            if (lane < 14) {
                int q = lane >> 1;
                ull* Tj = T + frow(lane);
                for (int kk2 = 0; kk2 <= q; kk2++) {
                    float lo = C[lane][2 * kk2];
                    float hi = (2 * kk2 + 1 <= lane) ? C[lane][2 * kk2 + 1] : 0.f;
                    Tj[kk2] = pk2(lo, hi);
                }
            }
        }
    }
    __syncthreads();              // prologue scratch dead; buffers may now be written

    // ========== main loop: double-buffered pipeline ==========
    const float* sS = (const float*)(S->tab + SPRIME_U);
    const ull neg1 = pk2(-1.f, -1.f);
    const int numTiles = (N + TILE - 1) / TILE;
    float acc = 0.f;
    int cur = 0;

    // prologue staging of first tile + its ids
    if (blockIdx.x < numTiles) {
        int cnt = min(TILE, N - blockIdx.x * TILE);
        stage(buf_u, buf_u + HALF_B,
              (const char*)A  + (size_t)blockIdx.x * TILE * ROW_B,
              (const char*)Bv + (size_t)blockIdx.x * TILE * ROW_B, cnt * ROW_B, tid);
    }
    asm volatile("cp.async.commit_group;");
    int cp0 = 0, cp1 = 0;
    if (blockIdx.x < numTiles) {
        int g0 = blockIdx.x * TILE + tid;
        int g1 = g0 + NTHR;
        if (g0 < N) cp0 = __ldg(ida + g0) * 4 + __ldg(idb + g0);
        if (g1 < N && tid + NTHR < TILE) cp1 = __ldg(ida + g1) * 4 + __ldg(idb + g1);
    }

    for (int tile = blockIdx.x; tile < numTiles; tile += gridDim.x) {
        const int cnt = min(TILE, N - tile * TILE);
        asm volatile("cp.async.wait_group 0;");
        __syncthreads();                                  // buffer ready, prev compute done

        // kick off next tile's copy into the other buffer
        const int nxt = tile + gridDim.x;
        const int nb = cur ^ 1;
        if (nxt < numTiles) {
            int ncnt = min(TILE, N - nxt * TILE);
            stage(buf_u + nb * BUF_SLOT, buf_u + nb * BUF_SLOT + HALF_B,
                  (const char*)A  + (size_t)nxt * TILE * ROW_B,
                  (const char*)Bv + (size_t)nxt * TILE * ROW_B, ncnt * ROW_B, tid);
        }
        asm volatile("cp.async.commit_group;");

        // histogram (ids already in regs)
        const bool act0 = tid < cnt;
        const bool act1 = tid + NTHR < cnt;
        if (act0) atomicAdd(&S->count[cp0], 1);
        if (act1) atomicAdd(&S->count[cp1], 1);

        // prefetch next tile's ids
        int np0 = 0, np1 = 0;
        if (nxt < numTiles) {
            int g0 = nxt * TILE + tid;
            int g1 = g0 + NTHR;
            if (g0 < N) np0 = __ldg(ida + g0) * 4 + __ldg(idb + g0);
            if (g1 < N && tid + NTHR < TILE) np1 = __ldg(ida + g1) * 4 + __ldg(idb + g1);
        }
        __syncthreads();

        // warp 0: prefix scan -> offsets + 64-row work items
        if (wid == 0) {
            int n = (lane < 16) ? S->count[lane] : 0;
            int nit = (n + 63) >> 6;
            int xs = n, xi = nit;
#pragma unroll
            for (int d = 1; d < 32; d <<= 1) {
                int ys = __shfl_up_sync(0xffffffffu, xs, d);
                int yi = __shfl_up_sync(0xffffffffu, xi, d);
                if (lane >= d) { xs += ys; xi += yi; }
            }
            int rowS = xs - n, itS = xi - nit;
            if (lane < 16) {
                S->ofs[lane] = rowS;
                for (int f = 0; f < nit; f++) {
                    S->wP[itS + f] = lane;
                    S->wO[itS + f] = rowS + f * 64;
                    S->wN[itS + f] = min(64, n - f * 64);
                }
            }
            if (lane == 15) S->num = xi;
            if (lane == 0)  S->item = 0;
        }
        __syncthreads();

        // scatter; clear counts for next tile
        if (act0) { int pos = atomicAdd(&S->ofs[cp0], 1); S->order[pos] = tid; }
        if (act1) { int pos = atomicAdd(&S->ofs[cp1], 1); S->order[pos] = tid + NTHR; }
        if (tid < 16) S->count[tid] = 0;
        __syncthreads();

        // compute: dynamic item grab, rows from staged smem
        const ull* bufA = (const ull*)(S->u.buf[cur]);
        const ull* bufB = bufA + TILE * 7;
        const int nItems = S->num;
        int it;
        if (lane == 0) it = atomicAdd(&S->item, 1);
        it = __shfl_sync(0xffffffffu, it, 0);
        while (it < nItems) {
            const int pp = S->wP[it], off = S->wO[it], n = S->wN[it];
            const bool v1 = lane < n;
            const bool v2 = 32 + lane < n;
            const int r1 = S->order[off + (v1 ? lane : 0)];
            const int r2 = S->order[off + (v2 ? 32 + lane : 0)];
            const ull* A1 = bufA + r1 * 7; const ull* B1 = bufB + r1 * 7;
            const ull* A2 = bufA + r2 * 7; const ull* B2 = bufB + r2 * 7;
            if (pp % 5 == 0) {
                const ull* T = S->tab + DIAG_BASE + (pp / 5) * DIAG_ULL;
                acc += (n > 32) ? eval_diag<true >(T, A1, B1, A2, B2, v1, v2, neg1)
                                : eval_diag<false>(T, A1, B1, A1, B1, v1, false, neg1);
            } else {
                const int slot = pp - pp / 5 - 1;
                const ull* T = S->tab + slot * OFF_ULL;
                const float sp = sS[pp];
                acc += (n > 32) ? eval_off<true >(T, sp, A1, B1, A2, B2, v1, v2)
                                : eval_off<false>(T, sp, A1, B1, A1, B1, v1, false);
            }
            if (lane == 0) it = atomicAdd(&S->item, 1);
            it = __shfl_sync(0xffffffffu, it, 0);
        }
        cp0 = np0; cp1 = np1; cur ^= 1;
    }

    // ---------- reduction + finalize (last CTA writes out, resets globals) ----
    __syncthreads();
#pragma unroll
    for (int off = 16; off; off >>= 1) acc += __shfl_xor_sync(0xffffffffu, acc, off);
    if (lane == 0) S->red[wid] = acc;
    __syncthreads();
    if (wid == 0) {
        float v = (lane < NWARP) ? S->red[lane] : 0.f;
#pragma unroll
        for (int off = 16; off; off >>= 1) v += __shfl_xor_sync(0xffffffffu, v, off);
        if (lane == 0) {
            atomicAdd(&g_sum, (double)v);
            __threadfence();
            int done = atomicAdd(&g_done, 1);
            if (done == (int)gridDim.x - 1) {
                double s = *((volatile double*)&g_sum);
                out[0] = (float)(s / ((double)N * 64.0));
                g_sum = 0.0;                 // reset for next graph replay
                g_done = 0;
            }
        }
    }
}

// ---------------------------------------------------------------------------

extern "C" void kernel_launch(void* const* d_in, const int* in_sizes, int n_in,
                              void* d_out, int out_size) {
    const float* A    = (const float*)d_in[0];   // (N,14)
    const float* B    = (const float*)d_in[1];   // (N,14)
    const int*   ia   = (const int*)d_in[2];     // (N,)
    const int*   ib   = (const int*)d_in[3];     // (N,)
    const float* W    = (const float*)d_in[4];   // (4,14,64)
    const float* bias = (const float*)d_in[5];   // (4,64)
    const int N = in_sizes[0] / 14;

    size_t smemBytes = sizeof(Smem) + 64;
    cudaFuncSetAttribute(fused_kernel, cudaFuncAttributeMaxDynamicSharedMemorySize,
                         (int)smemBytes);

    int sms = 148;
    cudaDeviceGetAttribute(&sms, cudaDevAttrMultiProcessorCount, 0);
    int numTiles = (N + TILE - 1) / TILE;
    int grid = numTiles < sms ? numTiles : sms;

    fused_kernel<<<grid, NTHR, smemBytes>>>(A, B, ia, ib, W, bias, N, (float*)d_out);
}